// round 2
// baseline (speedup 1.0000x reference)
#include <cuda_runtime.h>

#define NB 512   // buckets
#define ND 256   // feature dim

// Scratch (device globals: no allocation allowed)
__device__ float g_sums[NB * ND];
__device__ float g_counts[NB];
__device__ float g_gmean[ND];
__device__ float g_P2[NB * ND];   // (proto @ W_r^T), row-major [B][D]
__device__ int   g_idx_stride;    // 1 if bk is int32, 2 if int64 (read lo word)

// ---------------------------------------------------------------- dtype detect
// If bk is int64 (values < 512, little-endian), every odd 32-bit word is 0.
// If int32, odd words are random bucket ids; P(256 consecutive all zero) ~ 0.
__global__ void detect_kernel(const int* __restrict__ bk32, int n) {
    if (threadIdx.x == 0) {
        int acc = 0;
        int lim = min(256, n / 2);
        for (int i = 0; i < lim; i++) acc |= bk32[2 * i + 1];
        g_idx_stride = (acc != 0) ? 1 : 2;
    }
}

// ---------------------------------------------------------------- zero
__global__ void zero_kernel() {
    int i = blockIdx.x * blockDim.x + threadIdx.x;
    if (i < NB * ND) g_sums[i] = 0.f;
    if (i < NB) g_counts[i] = 0.f;
}

// ---------------------------------------------------------------- segment sums
// Grid: (16 col-groups of 16 cols, 28 row-chunks). Block: 256 threads.
// Each CTA privatizes sums for its 16 columns in smem (32KB), then merges.
__global__ void segsum_kernel(const float* __restrict__ V,
                              const int* __restrict__ bk32, int n) {
    __shared__ float ssum[NB * 16];
    int stride = g_idx_stride;
    int colg = blockIdx.x;  // cols [colg*16, colg*16+16)
    for (int i = threadIdx.x; i < NB * 16; i += blockDim.x) ssum[i] = 0.f;
    __syncthreads();
    int rowsPer = (n + gridDim.y - 1) / gridDim.y;
    int start = blockIdx.y * rowsPer;
    int end = min(start + rowsPer, n);
    int r = threadIdx.x >> 4;   // 0..15 rows per iteration
    int c = threadIdx.x & 15;
    for (int i = start + r; i < end; i += 16) {
        unsigned b = (unsigned)bk32[(size_t)i * stride];
        if (b < NB) {
            float v = V[(size_t)i * ND + colg * 16 + c];
            atomicAdd(&ssum[b * 16 + c], v);
        }
    }
    __syncthreads();
    for (int i = threadIdx.x; i < NB * 16; i += blockDim.x) {
        float s = ssum[i];
        if (s != 0.f)
            atomicAdd(&g_sums[(size_t)(i >> 4) * ND + colg * 16 + (i & 15)], s);
    }
}

// ---------------------------------------------------------------- counts
__global__ void counts_kernel(const int* __restrict__ bk32, int n) {
    __shared__ float sc[NB];
    int stride = g_idx_stride;
    for (int i = threadIdx.x; i < NB; i += blockDim.x) sc[i] = 0.f;
    __syncthreads();
    int rowsPer = (n + gridDim.x - 1) / gridDim.x;
    int start = blockIdx.x * rowsPer;
    int end = min(start + rowsPer, n);
    for (int i = start + threadIdx.x; i < end; i += blockDim.x) {
        unsigned b = (unsigned)bk32[(size_t)i * stride];
        if (b < NB) atomicAdd(&sc[b], 1.f);
    }
    __syncthreads();
    for (int i = threadIdx.x; i < NB; i += blockDim.x)
        if (sc[i] != 0.f) atomicAdd(&g_counts[i], sc[i]);
}

// ---------------------------------------------------------------- global mean
// global_mean = (sum over buckets of g_sums) / n   (every row is in some bucket)
__global__ void gmean_kernel(int n) {
    __shared__ float red[8][32];
    int lane = threadIdx.x & 31, part = threadIdx.x >> 5;
    int c = blockIdx.x * 32 + lane;
    float s = 0.f;
    for (int b = part * 64; b < part * 64 + 64; b++) s += g_sums[(size_t)b * ND + c];
    red[part][lane] = s;
    __syncthreads();
    if (part == 0) {
        float t = 0.f;
#pragma unroll
        for (int k = 0; k < 8; k++) t += red[k][lane];
        g_gmean[c] = t / (float)n;
    }
}

// ---------------------------------------------------------------- P2 = proto @ W_r^T
// P2[b][d2] = sum_d proto[b][d] * W_r[d2][d]
__global__ void p2_kernel(const float* __restrict__ Wr) {
    __shared__ __align__(16) float sp[ND];
    int b = blockIdx.x, t = threadIdx.x;
    float cnt = g_counts[b];
    sp[t] = (cnt > 0.f) ? g_sums[(size_t)b * ND + t] / cnt : g_gmean[t];
    __syncthreads();
    const float4* w4 = (const float4*)(Wr + (size_t)t * ND);
    const float4* p4 = (const float4*)sp;
    float acc = 0.f;
#pragma unroll 8
    for (int d = 0; d < ND / 4; d++) {
        float4 a = p4[d], w = w4[d];
        acc += a.x * w.x + a.y * w.y + a.z * w.z + a.w * w.w;
    }
    g_P2[(size_t)b * ND + t] = acc;
}

// ---------------------------------------------------------------- fused main
// Per CTA: 16 rows. Phase A: softmax stats (keep unnormalized exp in smem,
// fold 1/Z and gate into per-row coef). Phase B: GEMM tile 16x256 over K=512
// against L2-resident P2, thread tile 4x4. Phase C: add h_fused, LayerNorm.
__global__ __launch_bounds__(256) void main_kernel(
    const float* __restrict__ logits, const float* __restrict__ hfused,
    const float* __restrict__ gamma, const float* __restrict__ beta,
    float* __restrict__ outh, float* __restrict__ outc, int n) {
    __shared__ __align__(16) float sP[16 * NB];   // exp(l - m), later reused as sH
    __shared__ float sCoef[16];
    int row0 = blockIdx.x * 16;
    int tid = threadIdx.x, lane = tid & 31, warp = tid >> 5;

    // ---- Phase A: per-row softmax stats (warp handles 2 rows)
#pragma unroll
    for (int rr = 0; rr < 2; rr++) {
        int r = warp * 2 + rr;
        int row = row0 + r;
        if (row < n) {
            const float* lrow = logits + (size_t)row * NB;
            float v[16];
            float m = -1e30f;
#pragma unroll
            for (int k = 0; k < 16; k++) { v[k] = lrow[lane + 32 * k]; m = fmaxf(m, v[k]); }
#pragma unroll
            for (int o = 16; o; o >>= 1) m = fmaxf(m, __shfl_xor_sync(0xffffffffu, m, o));
            float Z = 0.f, S = 0.f;
#pragma unroll
            for (int k = 0; k < 16; k++) {
                float t = v[k] - m;
                float e = __expf(t);
                Z += e; S += e * t;
                sP[r * NB + lane + 32 * k] = e;
            }
#pragma unroll
            for (int o = 16; o; o >>= 1) {
                Z += __shfl_xor_sync(0xffffffffu, Z, o);
                S += __shfl_xor_sync(0xffffffffu, S, o);
            }
            float logZ = __logf(Z);
            float entropy = logZ - S / Z;                  // = -sum p log p
            float conf = 1.f - entropy * 0.16029938f;      // 1/ln(512)
            if (lane == 0) {
                sCoef[r] = (1.f - conf) / Z;               // gate / Z
                outc[row] = conf;
            }
        }
    }
    __syncthreads();

    // ---- Phase B: acc[r][c] = sum_b ehat[r][b] * P2[b][c]
    int cg = tid & 63, rg = tid >> 6;
    float acc[4][4];
#pragma unroll
    for (int r = 0; r < 4; r++)
#pragma unroll
        for (int c = 0; c < 4; c++) acc[r][c] = 0.f;

    const float4* P2v = (const float4*)g_P2;   // [b][64] float4
    const float4* sPv = (const float4*)sP;     // [r][128] float4
#pragma unroll 2
    for (int b4 = 0; b4 < NB / 4; b4++) {
        float4 w0 = P2v[(size_t)(4 * b4 + 0) * 64 + cg];
        float4 w1 = P2v[(size_t)(4 * b4 + 1) * 64 + cg];
        float4 w2 = P2v[(size_t)(4 * b4 + 2) * 64 + cg];
        float4 w3 = P2v[(size_t)(4 * b4 + 3) * 64 + cg];
#pragma unroll
        for (int r = 0; r < 4; r++) {
            float4 p = sPv[(rg * 4 + r) * (NB / 4) + b4];
            acc[r][0] += p.x * w0.x + p.y * w1.x + p.z * w2.x + p.w * w3.x;
            acc[r][1] += p.x * w0.y + p.y * w1.y + p.z * w2.y + p.w * w3.y;
            acc[r][2] += p.x * w0.z + p.y * w1.z + p.z * w2.z + p.w * w3.z;
            acc[r][3] += p.x * w0.w + p.y * w1.w + p.z * w2.w + p.w * w3.w;
        }
    }
    __syncthreads();

    // ---- Phase C: h = h_fused + coef * acc, stage into smem (reuse sP)
    float* sH = sP;
#pragma unroll
    for (int r = 0; r < 4; r++) {
        int row = rg * 4 + r;
        if (row0 + row < n) {
            float coef = sCoef[row];
            float4 hf = *(const float4*)(hfused + (size_t)(row0 + row) * ND + cg * 4);
            float4 h;
            h.x = hf.x + coef * acc[r][0];
            h.y = hf.y + coef * acc[r][1];
            h.z = hf.z + coef * acc[r][2];
            h.w = hf.w + coef * acc[r][3];
            *(float4*)(sH + row * ND + cg * 4) = h;
        }
    }
    __syncthreads();

    // ---- LayerNorm per row (warp handles 2 rows), biased variance, eps=1e-5
#pragma unroll
    for (int rr = 0; rr < 2; rr++) {
        int r = warp * 2 + rr;
        int row = row0 + r;
        if (row < n) {
            float x[8];
            float s = 0.f, s2 = 0.f;
#pragma unroll
            for (int k = 0; k < 8; k++) {
                x[k] = sH[r * ND + lane + 32 * k];
                s += x[k]; s2 += x[k] * x[k];
            }
#pragma unroll
            for (int o = 16; o; o >>= 1) {
                s += __shfl_xor_sync(0xffffffffu, s, o);
                s2 += __shfl_xor_sync(0xffffffffu, s2, o);
            }
            float mean = s * (1.f / ND);
            float var = s2 * (1.f / ND) - mean * mean;
            float rstd = rsqrtf(var + 1e-5f);
            float* orow = outh + (size_t)row * ND;
#pragma unroll
            for (int k = 0; k < 8; k++) {
                int c = lane + 32 * k;
                orow[c] = (x[k] - mean) * rstd * gamma[c] + beta[c];
            }
        }
    }
}

// ---------------------------------------------------------------- launch
extern "C" void kernel_launch(void* const* d_in, const int* in_sizes, int n_in,
                              void* d_out, int out_size) {
    const float* h_fused    = (const float*)d_in[0];
    const float* V          = (const float*)d_in[1];
    const float* logits     = (const float*)d_in[2];
    const int*   bk32       = (const int*)d_in[3];   // int32 or int64 (auto-detected)
    const float* Wr         = (const float*)d_in[4];
    const float* gamma      = (const float*)d_in[5];
    const float* beta       = (const float*)d_in[6];
    int n = in_sizes[0] / ND;

    float* outh = (float*)d_out;                 // (N, D) h_norm
    float* outc = outh + (size_t)n * ND;         // (N,)  confidence

    detect_kernel<<<1, 32>>>(bk32, n);
    zero_kernel<<<(NB * ND + 255) / 256, 256>>>();
    segsum_kernel<<<dim3(16, 28), 256>>>(V, bk32, n);
    counts_kernel<<<56, 256>>>(bk32, n);
    gmean_kernel<<<8, 256>>>(n);
    p2_kernel<<<NB, 256>>>(Wr);
    main_kernel<<<(n + 15) / 16, 256>>>(logits, h_fused, gamma, beta, outh, outc, n);
}

// round 3
// speedup vs baseline: 1.6172x; 1.6172x over previous
#include <cuda_runtime.h>

#define NB 512   // buckets
#define ND 256   // feature dim

#define SE_STRIDE 516   // 64-row exp tile, pad for conflict-free A frags
#define SB_STRIDE 264   // K-panel, pad for conflict-free B frags
#define SMEM_WORDS (64 * SE_STRIDE + 64 * SB_STRIDE + 64)
#define SMEM_BYTES (SMEM_WORDS * 4)

// Scratch (device globals: no allocation allowed)
__device__ float g_sums[NB * ND];
__device__ float g_counts[NB];
__device__ float g_gmean[ND];
__device__ float g_P2[NB * ND];   // (proto @ W_r^T), row-major [B][D]
__device__ int   g_idx_stride;    // 1 if bk is int32, 2 if int64 (read lo word)

__device__ __forceinline__ unsigned f2tf32(float x) {
    unsigned u;
    asm("cvt.rna.tf32.f32 %0, %1;" : "=r"(u) : "f"(x));
    return u;
}

__device__ __forceinline__ void mma_tf32(float* c, const unsigned* a,
                                         unsigned b0, unsigned b1) {
    asm("mma.sync.aligned.m16n8k8.row.col.f32.tf32.tf32.f32 "
        "{%0,%1,%2,%3},{%4,%5,%6,%7},{%8,%9},{%0,%1,%2,%3};"
        : "+f"(c[0]), "+f"(c[1]), "+f"(c[2]), "+f"(c[3])
        : "r"(a[0]), "r"(a[1]), "r"(a[2]), "r"(a[3]), "r"(b0), "r"(b1));
}

// ---------------------------------------------------------------- dtype detect
__global__ void detect_kernel(const int* __restrict__ bk32, int n) {
    if (threadIdx.x == 0) {
        int acc = 0;
        int lim = min(256, n / 2);
        for (int i = 0; i < lim; i++) acc |= bk32[2 * i + 1];
        g_idx_stride = (acc != 0) ? 1 : 2;
    }
}

// ---------------------------------------------------------------- zero
__global__ void zero_kernel() {
    int i = blockIdx.x * blockDim.x + threadIdx.x;
    if (i < NB * ND) g_sums[i] = 0.f;
    if (i < NB) g_counts[i] = 0.f;
}

// ---------------------------------------------------------------- segment sums
__global__ void segsum_kernel(const float* __restrict__ V,
                              const int* __restrict__ bk32, int n) {
    __shared__ float ssum[NB * 16];
    int stride = g_idx_stride;
    int colg = blockIdx.x;
    for (int i = threadIdx.x; i < NB * 16; i += blockDim.x) ssum[i] = 0.f;
    __syncthreads();
    int rowsPer = (n + gridDim.y - 1) / gridDim.y;
    int start = blockIdx.y * rowsPer;
    int end = min(start + rowsPer, n);
    int r = threadIdx.x >> 4;
    int c = threadIdx.x & 15;
    for (int i = start + r; i < end; i += 16) {
        unsigned b = (unsigned)bk32[(size_t)i * stride];
        if (b < NB) {
            float v = V[(size_t)i * ND + colg * 16 + c];
            atomicAdd(&ssum[b * 16 + c], v);
        }
    }
    __syncthreads();
    for (int i = threadIdx.x; i < NB * 16; i += blockDim.x) {
        float s = ssum[i];
        if (s != 0.f)
            atomicAdd(&g_sums[(size_t)(i >> 4) * ND + colg * 16 + (i & 15)], s);
    }
}

// ---------------------------------------------------------------- counts
__global__ void counts_kernel(const int* __restrict__ bk32, int n) {
    __shared__ float sc[NB];
    int stride = g_idx_stride;
    for (int i = threadIdx.x; i < NB; i += blockDim.x) sc[i] = 0.f;
    __syncthreads();
    int rowsPer = (n + gridDim.x - 1) / gridDim.x;
    int start = blockIdx.x * rowsPer;
    int end = min(start + rowsPer, n);
    for (int i = start + threadIdx.x; i < end; i += blockDim.x) {
        unsigned b = (unsigned)bk32[(size_t)i * stride];
        if (b < NB) atomicAdd(&sc[b], 1.f);
    }
    __syncthreads();
    for (int i = threadIdx.x; i < NB; i += blockDim.x)
        if (sc[i] != 0.f) atomicAdd(&g_counts[i], sc[i]);
}

// ---------------------------------------------------------------- global mean
__global__ void gmean_kernel(int n) {
    __shared__ float red[8][32];
    int lane = threadIdx.x & 31, part = threadIdx.x >> 5;
    int c = blockIdx.x * 32 + lane;
    float s = 0.f;
    for (int b = part * 64; b < part * 64 + 64; b++) s += g_sums[(size_t)b * ND + c];
    red[part][lane] = s;
    __syncthreads();
    if (part == 0) {
        float t = 0.f;
#pragma unroll
        for (int k = 0; k < 8; k++) t += red[k][lane];
        g_gmean[c] = t / (float)n;
    }
}

// ---------------------------------------------------------------- P2 = proto @ W_r^T
__global__ void p2_kernel(const float* __restrict__ Wr) {
    __shared__ __align__(16) float sp[ND];
    int b = blockIdx.x, t = threadIdx.x;
    float cnt = g_counts[b];
    sp[t] = (cnt > 0.f) ? g_sums[(size_t)b * ND + t] / cnt : g_gmean[t];
    __syncthreads();
    const float4* w4 = (const float4*)(Wr + (size_t)t * ND);
    const float4* p4 = (const float4*)sp;
    float acc = 0.f;
#pragma unroll 8
    for (int d = 0; d < ND / 4; d++) {
        float4 a = p4[d], w = w4[d];
        acc += a.x * w.x + a.y * w.y + a.z * w.z + a.w * w.w;
    }
    g_P2[(size_t)b * ND + t] = acc;
}

// ---------------------------------------------------------------- fused main (tf32 MMA)
// CTA: 64 rows. Phase A: softmax stats, store tf32-rounded exp to smem.
// Phase B: 64x256x512 GEMM via mma.sync m16n8k8 tf32 (8 warps, 64x32 warp tiles,
// K staged in 64-wide panels). Phase C: gate+add h_fused, LayerNorm.
__global__ __launch_bounds__(256, 1) void main_kernel(
    const float* __restrict__ logits, const float* __restrict__ hfused,
    const float* __restrict__ gamma, const float* __restrict__ beta,
    float* __restrict__ outh, float* __restrict__ outc, int n) {
    extern __shared__ unsigned smem_u[];
    unsigned* sE = smem_u;                               // [64][SE_STRIDE] tf32 bits
    unsigned* sB = smem_u + 64 * SE_STRIDE;              // [64][SB_STRIDE] tf32 bits
    float* sCoef = (float*)(smem_u + 64 * SE_STRIDE + 64 * SB_STRIDE);

    int row0 = blockIdx.x * 64;
    int tid = threadIdx.x, lane = tid & 31, warp = tid >> 5;
    int g = lane >> 2, tg = lane & 3;

    // ---- Phase A: per-row softmax stats (each warp: 8 rows)
#pragma unroll
    for (int rr = 0; rr < 8; rr++) {
        int r = warp * 8 + rr;
        int row = row0 + r;
        if (row < n) {
            const float* lrow = logits + (size_t)row * NB;
            float v[16];
            float m = -1e30f;
#pragma unroll
            for (int k = 0; k < 16; k++) { v[k] = lrow[lane + 32 * k]; m = fmaxf(m, v[k]); }
#pragma unroll
            for (int o = 16; o; o >>= 1) m = fmaxf(m, __shfl_xor_sync(0xffffffffu, m, o));
            float Z = 0.f, S = 0.f;
#pragma unroll
            for (int k = 0; k < 16; k++) {
                float t = v[k] - m;
                float e = __expf(t);
                Z += e; S += e * t;
                sE[r * SE_STRIDE + lane + 32 * k] = f2tf32(e);
            }
#pragma unroll
            for (int o = 16; o; o >>= 1) {
                Z += __shfl_xor_sync(0xffffffffu, Z, o);
                S += __shfl_xor_sync(0xffffffffu, S, o);
            }
            float logZ = __logf(Z);
            float entropy = logZ - S / Z;
            float conf = 1.f - entropy * 0.16029938f;     // 1/ln(512)
            if (lane == 0) {
                sCoef[r] = (1.f - conf) / Z;              // gate / Z
                outc[row] = conf;
            }
        } else {
#pragma unroll
            for (int k = 0; k < 16; k++) sE[r * SE_STRIDE + lane + 32 * k] = 0u;
        }
    }
    __syncthreads();

    // ---- Phase B: acc = ehat @ P2 via tf32 MMA. warp w: cols [w*32, w*32+32)
    float acc[4][4][4];
#pragma unroll
    for (int mt = 0; mt < 4; mt++)
#pragma unroll
        for (int nt = 0; nt < 4; nt++)
#pragma unroll
            for (int q = 0; q < 4; q++) acc[mt][nt][q] = 0.f;

    int colbase = warp * 32;
    for (int kc = 0; kc < 8; kc++) {
        // cooperative load of P2 panel [64 k][256 cols] with tf32 rounding
#pragma unroll
        for (int i = 0; i < 16; i++) {
            int q = tid + i * 256;
            int k = q >> 6;
            int c4 = (q & 63) << 2;
            float4 p = *(const float4*)(g_P2 + ((size_t)(kc * 64 + k)) * ND + c4);
            unsigned* dst = sB + k * SB_STRIDE + c4;
            dst[0] = f2tf32(p.x); dst[1] = f2tf32(p.y);
            dst[2] = f2tf32(p.z); dst[3] = f2tf32(p.w);
        }
        __syncthreads();
#pragma unroll
        for (int ks = 0; ks < 8; ks++) {
            int kk = kc * 64 + ks * 8;
            int kl = ks * 8;
            unsigned a[4][4];
#pragma unroll
            for (int mt = 0; mt < 4; mt++) {
                int rb = mt * 16;
                a[mt][0] = sE[(rb + g) * SE_STRIDE + kk + tg];
                a[mt][1] = sE[(rb + g + 8) * SE_STRIDE + kk + tg];
                a[mt][2] = sE[(rb + g) * SE_STRIDE + kk + tg + 4];
                a[mt][3] = sE[(rb + g + 8) * SE_STRIDE + kk + tg + 4];
            }
#pragma unroll
            for (int nt = 0; nt < 4; nt++) {
                int coln = colbase + nt * 8 + g;
                unsigned b0 = sB[(kl + tg) * SB_STRIDE + coln];
                unsigned b1 = sB[(kl + tg + 4) * SB_STRIDE + coln];
#pragma unroll
                for (int mt = 0; mt < 4; mt++) mma_tf32(acc[mt][nt], a[mt], b0, b1);
            }
        }
        __syncthreads();
    }

    // ---- Phase C: fragments -> smem (reuse sE region as fp32 [64][SB_STRIDE])
    float* sH = (float*)smem_u;
#pragma unroll
    for (int mt = 0; mt < 4; mt++) {
        int rb = mt * 16;
#pragma unroll
        for (int nt = 0; nt < 4; nt++) {
            int cb = colbase + nt * 8 + 2 * tg;
            sH[(rb + g) * SB_STRIDE + cb]         = acc[mt][nt][0];
            sH[(rb + g) * SB_STRIDE + cb + 1]     = acc[mt][nt][1];
            sH[(rb + g + 8) * SB_STRIDE + cb]     = acc[mt][nt][2];
            sH[(rb + g + 8) * SB_STRIDE + cb + 1] = acc[mt][nt][3];
        }
    }
    __syncthreads();

    // ---- LayerNorm per row (each warp: 8 rows)
    float gam[8], bet[8];
#pragma unroll
    for (int k = 0; k < 8; k++) { gam[k] = gamma[lane + 32 * k]; bet[k] = beta[lane + 32 * k]; }
#pragma unroll
    for (int rr = 0; rr < 8; rr++) {
        int r = warp * 8 + rr;
        int row = row0 + r;
        if (row < n) {
            float coef = sCoef[r];
            const float* hrow = hfused + (size_t)row * ND;
            float x[8];
            float s = 0.f, s2 = 0.f;
#pragma unroll
            for (int k = 0; k < 8; k++) {
                int c = lane + 32 * k;
                x[k] = hrow[c] + coef * sH[r * SB_STRIDE + c];
                s += x[k]; s2 += x[k] * x[k];
            }
#pragma unroll
            for (int o = 16; o; o >>= 1) {
                s += __shfl_xor_sync(0xffffffffu, s, o);
                s2 += __shfl_xor_sync(0xffffffffu, s2, o);
            }
            float mean = s * (1.f / ND);
            float var = s2 * (1.f / ND) - mean * mean;
            float rstd = rsqrtf(var + 1e-5f);
            float* orow = outh + (size_t)row * ND;
#pragma unroll
            for (int k = 0; k < 8; k++) {
                int c = lane + 32 * k;
                orow[c] = (x[k] - mean) * rstd * gam[k] + bet[k];
            }
        }
    }
}

// ---------------------------------------------------------------- launch
extern "C" void kernel_launch(void* const* d_in, const int* in_sizes, int n_in,
                              void* d_out, int out_size) {
    const float* h_fused    = (const float*)d_in[0];
    const float* V          = (const float*)d_in[1];
    const float* logits     = (const float*)d_in[2];
    const int*   bk32       = (const int*)d_in[3];
    const float* Wr         = (const float*)d_in[4];
    const float* gamma      = (const float*)d_in[5];
    const float* beta       = (const float*)d_in[6];
    int n = in_sizes[0] / ND;

    float* outh = (float*)d_out;
    float* outc = outh + (size_t)n * ND;

    cudaFuncSetAttribute(main_kernel, cudaFuncAttributeMaxDynamicSharedMemorySize,
                         SMEM_BYTES);

    detect_kernel<<<1, 32>>>(bk32, n);
    zero_kernel<<<(NB * ND + 255) / 256, 256>>>();
    segsum_kernel<<<dim3(16, 28), 256>>>(V, bk32, n);
    counts_kernel<<<56, 256>>>(bk32, n);
    gmean_kernel<<<8, 256>>>(n);
    p2_kernel<<<NB, 256>>>(Wr);
    main_kernel<<<(n + 63) / 64, 256, SMEM_BYTES>>>(logits, h_fused, gamma, beta,
                                                    outh, outc, n);
}

// round 4
// speedup vs baseline: 2.9903x; 1.8490x over previous
#include <cuda_runtime.h>
#include <cuda_fp16.h>

#define NB 512   // buckets
#define ND 256   // feature dim
#define NMAX 100352

#define SE_STRIDE 520   // halves per row of exp tile (512 + 8 pad)
#define SB_STRIDE 72    // halves per row of B^T panel (64 + 8 pad)
#define SMEM_BYTES ((64 * SE_STRIDE + 256 * SB_STRIDE) * 2 + 64 * 4)

// Scratch (device globals: no allocation allowed)
__device__ float g_sums[NB * ND];
__device__ float g_counts[NB];
__device__ float g_gmean[ND];
__device__ __align__(16) __half g_P2t[ND * NB];  // (proto @ W_r^T)^T fp16, [d2][b]
__device__ int   g_cnt[NB];
__device__ int   g_off[NB + 1];
__device__ int   g_cursor[NB];
__device__ int   g_perm[NMAX];
__device__ int   g_idx_stride;    // 1 if bk is int32, 2 if int64 (read lo word)

__device__ __forceinline__ void mma_f16(float* c, const unsigned* a,
                                        unsigned b0, unsigned b1) {
    asm("mma.sync.aligned.m16n8k16.row.col.f32.f16.f16.f32 "
        "{%0,%1,%2,%3},{%4,%5,%6,%7},{%8,%9},{%0,%1,%2,%3};"
        : "+f"(c[0]), "+f"(c[1]), "+f"(c[2]), "+f"(c[3])
        : "r"(a[0]), "r"(a[1]), "r"(a[2]), "r"(a[3]), "r"(b0), "r"(b1));
}

// ---------------------------------------------------------------- dtype detect
__global__ void detect_kernel(const int* __restrict__ bk32, int n) {
    if (threadIdx.x == 0) {
        int acc = 0;
        int lim = min(256, n / 2);
        for (int i = 0; i < lim; i++) acc |= bk32[2 * i + 1];
        g_idx_stride = (acc != 0) ? 1 : 2;
    }
}

// ---------------------------------------------------------------- zero counts
__global__ void zero_kernel() {
    int i = threadIdx.x;
    if (i < NB) g_cnt[i] = 0;
}

// ---------------------------------------------------------------- int counts
__global__ void counts_kernel(const int* __restrict__ bk32, int n) {
    __shared__ int sc[NB];
    int stride = g_idx_stride;
    for (int i = threadIdx.x; i < NB; i += blockDim.x) sc[i] = 0;
    __syncthreads();
    int i0 = blockIdx.x * blockDim.x * 8 + threadIdx.x;
    for (int k = 0; k < 8; k++) {
        int i = i0 + k * blockDim.x;
        if (i < n) {
            unsigned b = (unsigned)bk32[(size_t)i * stride];
            if (b < NB) atomicAdd(&sc[b], 1);
        }
    }
    __syncthreads();
    for (int i = threadIdx.x; i < NB; i += blockDim.x)
        if (sc[i] != 0) atomicAdd(&g_cnt[i], sc[i]);
}

// ---------------------------------------------------------------- scan (1 CTA)
__global__ void scan_kernel(int n) {
    __shared__ int s[NB];
    int t = threadIdx.x;
    int cnt = g_cnt[t];
    s[t] = cnt;
    __syncthreads();
#pragma unroll
    for (int o = 1; o < NB; o <<= 1) {
        int v = (t >= o) ? s[t - o] : 0;
        __syncthreads();
        s[t] += v;
        __syncthreads();
    }
    int excl = s[t] - cnt;
    g_off[t] = excl;
    g_cursor[t] = excl;
    g_counts[t] = (float)cnt;
    if (t == NB - 1) g_off[NB] = s[t];
}

// ---------------------------------------------------------------- scatter perm
__global__ void scatter_kernel(const int* __restrict__ bk32, int n) {
    int stride = g_idx_stride;
    int i = blockIdx.x * blockDim.x + threadIdx.x;
    if (i < n) {
        unsigned b = (unsigned)bk32[(size_t)i * stride];
        if (b < NB) {
            int pos = atomicAdd(&g_cursor[b], 1);
            if ((unsigned)pos < (unsigned)n) g_perm[pos] = i;
        }
    }
}

// ---------------------------------------------------------------- bucket sums
// CTA b: thread t owns column t; plain register accumulation, no atomics.
__global__ __launch_bounds__(256) void bucket_sum_kernel(const float* __restrict__ V) {
    int b = blockIdx.x, t = threadIdx.x;
    int s0 = g_off[b], s1 = g_off[b + 1];
    float acc = 0.f;
    int i = s0;
    for (; i + 8 <= s1; i += 8) {
        int r[8];
#pragma unroll
        for (int j = 0; j < 8; j++) r[j] = g_perm[i + j];
#pragma unroll
        for (int j = 0; j < 8; j++) acc += V[(size_t)r[j] * ND + t];
    }
    for (; i < s1; i++) acc += V[(size_t)g_perm[i] * ND + t];
    g_sums[b * ND + t] = acc;
}

// ---------------------------------------------------------------- global mean
__global__ void gmean_kernel(int n) {
    __shared__ float red[8][32];
    int lane = threadIdx.x & 31, part = threadIdx.x >> 5;
    int c = blockIdx.x * 32 + lane;
    float s = 0.f;
    for (int b = part * 64; b < part * 64 + 64; b++) s += g_sums[(size_t)b * ND + c];
    red[part][lane] = s;
    __syncthreads();
    if (part == 0) {
        float t = 0.f;
#pragma unroll
        for (int k = 0; k < 8; k++) t += red[k][lane];
        g_gmean[c] = t / (float)n;
    }
}

// ---------------------------------------------------------------- P2^T (fp16)
// g_P2t[d2][b] = sum_d proto[b][d] * W_r[d2][d]
__global__ void p2_kernel(const float* __restrict__ Wr) {
    __shared__ __align__(16) float sp[ND];
    int b = blockIdx.x, t = threadIdx.x;
    float cnt = g_counts[b];
    sp[t] = (cnt > 0.f) ? g_sums[(size_t)b * ND + t] / cnt : g_gmean[t];
    __syncthreads();
    const float4* w4 = (const float4*)(Wr + (size_t)t * ND);
    const float4* p4 = (const float4*)sp;
    float acc = 0.f;
#pragma unroll 8
    for (int d = 0; d < ND / 4; d++) {
        float4 a = p4[d], w = w4[d];
        acc += a.x * w.x + a.y * w.y + a.z * w.z + a.w * w.w;
    }
    g_P2t[(size_t)t * NB + b] = __float2half(acc);
}

// ---------------------------------------------------------------- fused main (fp16 MMA)
// CTA: 64 rows. Phase A: softmax stats -> fp16 exp tile in smem.
// Phase B: 64x256x512 GEMM, mma m16n8k16 f16 (8 warps, 64x32 warp tiles,
// B^T panels of K=64 staged from g_P2t). Phase C: gate+add, LayerNorm.
__global__ __launch_bounds__(256, 2) void main_kernel(
    const float* __restrict__ logits, const float* __restrict__ hfused,
    const float* __restrict__ gamma, const float* __restrict__ beta,
    float* __restrict__ outh, float* __restrict__ outc, int n) {
    extern __shared__ __align__(16) __half smem_h[];
    __half* sE = smem_h;                             // [64][SE_STRIDE]
    __half* sB = smem_h + 64 * SE_STRIDE;            // [256][SB_STRIDE] (B^T)
    float* sCoef = (float*)(sB + 256 * SB_STRIDE);   // [64]

    int row0 = blockIdx.x * 64;
    int tid = threadIdx.x, lane = tid & 31, warp = tid >> 5;
    int g = lane >> 2, tg = lane & 3;

    // ---- Phase A: per-row softmax stats (each warp: 8 rows; lane owns 16 cols)
#pragma unroll
    for (int rr = 0; rr < 8; rr++) {
        int r = warp * 8 + rr;
        int row = row0 + r;
        uint4* dst = (uint4*)(sE + r * SE_STRIDE + lane * 16);
        if (row < n) {
            const float* lrow = logits + (size_t)row * NB + lane * 16;
            float v[16];
#pragma unroll
            for (int q = 0; q < 4; q++) {
                float4 f = *(const float4*)(lrow + 4 * q);
                v[4 * q] = f.x; v[4 * q + 1] = f.y; v[4 * q + 2] = f.z; v[4 * q + 3] = f.w;
            }
            float m = v[0];
#pragma unroll
            for (int k = 1; k < 16; k++) m = fmaxf(m, v[k]);
#pragma unroll
            for (int o = 16; o; o >>= 1) m = fmaxf(m, __shfl_xor_sync(0xffffffffu, m, o));
            float Z = 0.f, S = 0.f;
            unsigned h[8];
#pragma unroll
            for (int k = 0; k < 8; k++) {
                float t0 = v[2 * k] - m, t1 = v[2 * k + 1] - m;
                float e0 = __expf(t0), e1 = __expf(t1);
                Z += e0 + e1; S += e0 * t0 + e1 * t1;
                __half2 p = __floats2half2_rn(e0, e1);
                h[k] = *(unsigned*)&p;
            }
#pragma unroll
            for (int o = 16; o; o >>= 1) {
                Z += __shfl_xor_sync(0xffffffffu, Z, o);
                S += __shfl_xor_sync(0xffffffffu, S, o);
            }
            dst[0] = make_uint4(h[0], h[1], h[2], h[3]);
            dst[1] = make_uint4(h[4], h[5], h[6], h[7]);
            float logZ = __logf(Z);
            float entropy = logZ - S / Z;
            float conf = 1.f - entropy * 0.16029938f;     // 1/ln(512)
            if (lane == 0) {
                sCoef[r] = (1.f - conf) / Z;              // gate / Z
                outc[row] = conf;
            }
        } else {
            dst[0] = make_uint4(0, 0, 0, 0);
            dst[1] = make_uint4(0, 0, 0, 0);
        }
    }
    __syncthreads();

    // ---- Phase B: acc = ehat @ P2. warp w: cols [w*32, w*32+32)
    float acc[4][4][4];
#pragma unroll
    for (int mt = 0; mt < 4; mt++)
#pragma unroll
        for (int nt = 0; nt < 4; nt++)
#pragma unroll
            for (int q = 0; q < 4; q++) acc[mt][nt][q] = 0.f;

    int colbase = warp * 32;
    const __half* P2t = g_P2t;
    for (int kc = 0; kc < 8; kc++) {
        // stage B^T panel: 256 n-rows x 64 k (16B per thread-slot, coalesced)
#pragma unroll
        for (int i = 0; i < 8; i++) {
            int idx = tid + i * 256;
            int nr = idx >> 3, seg = idx & 7;
            *(uint4*)(sB + nr * SB_STRIDE + seg * 8) =
                *(const uint4*)(P2t + (size_t)nr * NB + kc * 64 + seg * 8);
        }
        __syncthreads();
#pragma unroll
        for (int ks = 0; ks < 4; ks++) {
            int ka = kc * 64 + ks * 16 + 2 * tg;
            int kb = ks * 16 + 2 * tg;
            unsigned a[4][4];
#pragma unroll
            for (int mt = 0; mt < 4; mt++) {
                int rb = mt * 16;
                a[mt][0] = *(unsigned*)(sE + (rb + g) * SE_STRIDE + ka);
                a[mt][1] = *(unsigned*)(sE + (rb + g + 8) * SE_STRIDE + ka);
                a[mt][2] = *(unsigned*)(sE + (rb + g) * SE_STRIDE + ka + 8);
                a[mt][3] = *(unsigned*)(sE + (rb + g + 8) * SE_STRIDE + ka + 8);
            }
#pragma unroll
            for (int nt = 0; nt < 4; nt++) {
                int col = colbase + nt * 8 + g;
                unsigned b0 = *(unsigned*)(sB + col * SB_STRIDE + kb);
                unsigned b1 = *(unsigned*)(sB + col * SB_STRIDE + kb + 8);
#pragma unroll
                for (int mt = 0; mt < 4; mt++) mma_f16(acc[mt][nt], a[mt], b0, b1);
            }
        }
        __syncthreads();
    }

    // ---- Phase C: fragments -> smem fp32 [64][264] (reuses sE/sB region)
    float* sH = (float*)smem_h;
#pragma unroll
    for (int mt = 0; mt < 4; mt++) {
        int rb = mt * 16;
#pragma unroll
        for (int nt = 0; nt < 4; nt++) {
            int cb = colbase + nt * 8 + 2 * tg;
            sH[(rb + g) * 264 + cb]         = acc[mt][nt][0];
            sH[(rb + g) * 264 + cb + 1]     = acc[mt][nt][1];
            sH[(rb + g + 8) * 264 + cb]     = acc[mt][nt][2];
            sH[(rb + g + 8) * 264 + cb + 1] = acc[mt][nt][3];
        }
    }
    __syncthreads();

    // ---- LayerNorm per row (each warp: 8 rows)
    float gam[8], bet[8];
#pragma unroll
    for (int k = 0; k < 8; k++) { gam[k] = gamma[lane + 32 * k]; bet[k] = beta[lane + 32 * k]; }
#pragma unroll
    for (int rr = 0; rr < 8; rr++) {
        int r = warp * 8 + rr;
        int row = row0 + r;
        if (row < n) {
            float coef = sCoef[r];
            const float* hrow = hfused + (size_t)row * ND;
            float x[8];
            float s = 0.f, s2 = 0.f;
#pragma unroll
            for (int k = 0; k < 8; k++) {
                int c = lane + 32 * k;
                x[k] = hrow[c] + coef * sH[r * 264 + c];
                s += x[k]; s2 += x[k] * x[k];
            }
#pragma unroll
            for (int o = 16; o; o >>= 1) {
                s += __shfl_xor_sync(0xffffffffu, s, o);
                s2 += __shfl_xor_sync(0xffffffffu, s2, o);
            }
            float mean = s * (1.f / ND);
            float var = s2 * (1.f / ND) - mean * mean;
            float rstd = rsqrtf(var + 1e-5f);
            float* orow = outh + (size_t)row * ND;
#pragma unroll
            for (int k = 0; k < 8; k++) {
                int c = lane + 32 * k;
                orow[c] = (x[k] - mean) * rstd * gam[k] + bet[k];
            }
        }
    }
}

// ---------------------------------------------------------------- launch
extern "C" void kernel_launch(void* const* d_in, const int* in_sizes, int n_in,
                              void* d_out, int out_size) {
    const float* h_fused    = (const float*)d_in[0];
    const float* V          = (const float*)d_in[1];
    const float* logits     = (const float*)d_in[2];
    const int*   bk32       = (const int*)d_in[3];
    const float* Wr         = (const float*)d_in[4];
    const float* gamma      = (const float*)d_in[5];
    const float* beta       = (const float*)d_in[6];
    int n = in_sizes[0] / ND;

    float* outh = (float*)d_out;
    float* outc = outh + (size_t)n * ND;

    cudaFuncSetAttribute(main_kernel, cudaFuncAttributeMaxDynamicSharedMemorySize,
                         SMEM_BYTES);

    detect_kernel<<<1, 32>>>(bk32, n);
    zero_kernel<<<1, NB>>>();
    counts_kernel<<<(n + 2047) / 2048, 256>>>(bk32, n);
    scan_kernel<<<1, NB>>>(n);
    scatter_kernel<<<(n + 511) / 512, 512>>>(bk32, n);
    bucket_sum_kernel<<<NB, 256>>>(V);
    gmean_kernel<<<8, 256>>>(n);
    p2_kernel<<<NB, 256>>>(Wr);
    main_kernel<<<(n + 63) / 64, 256, SMEM_BYTES>>>(logits, h_fused, gamma, beta,
                                                    outh, outc, n);
}

// round 9
// speedup vs baseline: 3.2142x; 1.0749x over previous
#include <cuda_runtime.h>
#include <cuda_fp16.h>
#include <cstdint>

#define NB 512   // buckets
#define ND 256   // feature dim
#define NMAX 100352
#define NCNT_BLK 56

#define SE_STRIDE 520          // halves per row of exp tile (512 + 8 pad)
#define SE_OFF 0               // 64 x 520 halves = 66560 B
#define SB_OFF 66560           // B double buffer: 2 x 20480 B (256 rows x 80 B)
#define SB_BUF 20480
#define XCOEF_OFF 107520       // 64 floats
#define SMEM_TOTAL (107520 + 256 + 32)
#define SH_STRIDE 264          // fp32 epilogue tile stride (overlaps sE/sB region)

// ---------------- device scratch (no allocation allowed) ----------------
__device__ float g_sums[NB * ND];
__device__ float g_counts[NB];
__device__ int   g_pcnt[NCNT_BLK][NB];
__device__ int   g_off[NB + 1];
__device__ int   g_cursor[NB];
__device__ int   g_perm[NMAX];
__device__ __align__(16) __half g_P2t[ND * NB];  // (proto @ W_r^T)^T fp16, [d2][b]

// ---------------- helpers ----------------
__device__ __forceinline__ uint32_t smem_u32(const void* p) {
    uint32_t a;
    asm("{ .reg .u64 t; cvta.to.shared.u64 t, %1; cvt.u32.u64 %0, t; }" : "=r"(a) : "l"(p));
    return a;
}
__device__ __forceinline__ void mma_f16(float* c, const unsigned* a,
                                        unsigned b0, unsigned b1) {
    asm("mma.sync.aligned.m16n8k16.row.col.f32.f16.f16.f32 "
        "{%0,%1,%2,%3},{%4,%5,%6,%7},{%8,%9},{%0,%1,%2,%3};"
        : "+f"(c[0]), "+f"(c[1]), "+f"(c[2]), "+f"(c[3])
        : "r"(a[0]), "r"(a[1]), "r"(a[2]), "r"(a[3]), "r"(b0), "r"(b1));
}
__device__ __forceinline__ void ldmatrix_x4(unsigned* r, uint32_t addr) {
    asm volatile("ldmatrix.sync.aligned.m8n8.x4.shared.b16 {%0,%1,%2,%3}, [%4];"
        : "=r"(r[0]), "=r"(r[1]), "=r"(r[2]), "=r"(r[3]) : "r"(addr));
}
#define CP_ASYNC16(dst, src) \
    asm volatile("cp.async.cg.shared.global [%0], [%1], 16;" :: "r"(dst), "l"(src))
#define CP_COMMIT() asm volatile("cp.async.commit_group;" ::: "memory")
#define CP_WAIT1()  asm volatile("cp.async.wait_group 1;" ::: "memory")

// ---------------- dtype detect (warp-parallel) ----------------
__device__ __forceinline__ int detect_stride(const int* __restrict__ bk, int n) {
    int lane = threadIdx.x & 31;
    int acc = 0;
    int lim = min(256, n / 2);
    for (int j = lane; j < lim; j += 32) acc |= bk[2 * j + 1];
#pragma unroll
    for (int o = 16; o; o >>= 1) acc |= __shfl_xor_sync(0xffffffffu, acc, o);
    return acc ? 1 : 2;
}

// ---------------- 1: per-block bucket counts ----------------
__global__ void counts_kernel(const int* __restrict__ bk, int n) {
    __shared__ int sc[NB];
    __shared__ int sstride;
    if (threadIdx.x < 32) {
        int s = detect_stride(bk, n);
        if (threadIdx.x == 0) sstride = s;
    }
    for (int i = threadIdx.x; i < NB; i += 256) sc[i] = 0;
    __syncthreads();
    int stride = sstride;
    for (int i = blockIdx.x * 256 + threadIdx.x; i < n; i += NCNT_BLK * 256) {
        unsigned b = (unsigned)bk[(size_t)i * stride];
        if (b < NB) atomicAdd(&sc[b], 1);
    }
    __syncthreads();
    for (int i = threadIdx.x; i < NB; i += 256) g_pcnt[blockIdx.x][i] = sc[i];
}

// ---------------- 2: reduce + scan (1 CTA) ----------------
__global__ void scan_kernel(int n) {
    __shared__ int s[NB];
    int t = threadIdx.x;
    int cnt = 0;
    for (int b = 0; b < NCNT_BLK; b++) cnt += g_pcnt[b][t];
    s[t] = cnt;
    __syncthreads();
#pragma unroll
    for (int o = 1; o < NB; o <<= 1) {
        int v = (t >= o) ? s[t - o] : 0;
        __syncthreads();
        s[t] += v;
        __syncthreads();
    }
    int excl = s[t] - cnt;
    g_off[t] = excl;
    g_cursor[t] = excl;
    g_counts[t] = (float)cnt;
    if (t == NB - 1) g_off[NB] = s[t];
}

// ---------------- 3: scatter permutation ----------------
__global__ void scatter_kernel(const int* __restrict__ bk, int n) {
    __shared__ int sstride;
    if (threadIdx.x < 32) {
        int s = detect_stride(bk, n);
        if (threadIdx.x == 0) sstride = s;
    }
    __syncthreads();
    int stride = sstride;
    int i = blockIdx.x * blockDim.x + threadIdx.x;
    if (i < n) {
        unsigned b = (unsigned)bk[(size_t)i * stride];
        if (b < NB) {
            int pos = atomicAdd(&g_cursor[b], 1);
            if ((unsigned)pos < (unsigned)NMAX) g_perm[pos] = i;
        }
    }
}

// ---------------- 4: per-bucket column sums (no atomics) ----------------
__global__ __launch_bounds__(256) void bucket_sum_kernel(const float* __restrict__ V) {
    int b = blockIdx.x, t = threadIdx.x;
    int s0 = g_off[b], s1 = g_off[b + 1];
    float acc = 0.f;
    int i = s0;
    for (; i + 8 <= s1; i += 8) {
        int r[8];
#pragma unroll
        for (int j = 0; j < 8; j++) r[j] = g_perm[i + j];
#pragma unroll
        for (int j = 0; j < 8; j++) acc += V[(size_t)r[j] * ND + t];
    }
    for (; i < s1; i++) acc += V[(size_t)g_perm[i] * ND + t];
    g_sums[b * ND + t] = acc;
}

// ---------------- 5: P2^T fp16 (with lazy global-mean fallback) ----------------
__global__ void p2_kernel(const float* __restrict__ Wr, int n) {
    __shared__ __align__(16) float sp[ND];
    int b = blockIdx.x, t = threadIdx.x;
    float cnt = g_counts[b];
    float val;
    if (cnt > 0.f) {
        val = g_sums[(size_t)b * ND + t] / cnt;
    } else {  // statistically never taken at N=100k, B=512; correct if it is
        float s = 0.f;
        for (int bb = 0; bb < NB; bb++) s += g_sums[(size_t)bb * ND + t];
        val = s / (float)n;
    }
    sp[t] = val;
    __syncthreads();
    const float4* w4 = (const float4*)(Wr + (size_t)t * ND);
    const float4* p4 = (const float4*)sp;
    float acc = 0.f;
#pragma unroll 8
    for (int d = 0; d < ND / 4; d++) {
        float4 a = p4[d], w = w4[d];
        acc += a.x * w.x + a.y * w.y + a.z * w.z + a.w * w.w;
    }
    g_P2t[(size_t)t * NB + b] = __float2half(acc);
}

// ---------------- 6: fused main (fp16 mma.sync + cp.async pipeline) ----------------
// CTA: 64 rows. Phase A: softmax -> fp16 exp tile (prefetch of B chunks 0,1
// already in flight). Phase B: 64x256x512 GEMM, m16n8k16, 16 K-chunks of 32,
// cp.async double-buffered. Phase C: gate+add h_fused, LayerNorm.
__global__ __launch_bounds__(256, 2) void main_kernel(
    const float* __restrict__ logits, const float* __restrict__ hfused,
    const float* __restrict__ gamma, const float* __restrict__ beta,
    float* __restrict__ outh, float* __restrict__ outc, int n) {
    extern __shared__ __align__(16) char smem[];
    __half* sE = (__half*)(smem + SE_OFF);
    float* sCoef = (float*)(smem + XCOEF_OFF);
    uint32_t sbase = smem_u32(smem);

    int row0 = blockIdx.x * 64;
    int tid = threadIdx.x, lane = tid & 31, warp = tid >> 5;
    int g = lane >> 2, tg = lane & 3;

    // ---- prefetch B chunks 0 and 1 (overlaps with Phase A) ----
    // chunk kc: [256 n-rows][32 k] halves; dst row stride 80B; 4x16B per thread.
    const char* P2c = (const char*)g_P2t;
#pragma unroll
    for (int c = 0; c < 2; c++) {
#pragma unroll
        for (int j = 0; j < 4; j++) {
            int idx = tid + j * 256;
            int nr = idx >> 2, seg = idx & 3;
            uint32_t dst = sbase + SB_OFF + c * SB_BUF + nr * 80 + seg * 16;
            const char* src = P2c + ((size_t)nr * NB + c * 32 + seg * 8) * 2;
            CP_ASYNC16(dst, src);
        }
        CP_COMMIT();
    }

    // ---- Phase A: per-row softmax stats (each warp: 8 rows; lane owns 16 cols)
#pragma unroll
    for (int rr = 0; rr < 8; rr++) {
        int r = warp * 8 + rr;
        int row = row0 + r;
        uint4* dst = (uint4*)(sE + r * SE_STRIDE + lane * 16);
        if (row < n) {
            const float* lrow = logits + (size_t)row * NB + lane * 16;
            float v[16];
#pragma unroll
            for (int q = 0; q < 4; q++) {
                float4 f = *(const float4*)(lrow + 4 * q);
                v[4 * q] = f.x; v[4 * q + 1] = f.y; v[4 * q + 2] = f.z; v[4 * q + 3] = f.w;
            }
            float m = v[0];
#pragma unroll
            for (int k = 1; k < 16; k++) m = fmaxf(m, v[k]);
#pragma unroll
            for (int o = 16; o; o >>= 1) m = fmaxf(m, __shfl_xor_sync(0xffffffffu, m, o));
            float Z = 0.f, S = 0.f;
            unsigned h[8];
#pragma unroll
            for (int k = 0; k < 8; k++) {
                float t0 = v[2 * k] - m, t1 = v[2 * k + 1] - m;
                float e0 = __expf(t0), e1 = __expf(t1);
                Z += e0 + e1; S += e0 * t0 + e1 * t1;
                __half2 p = __floats2half2_rn(e0, e1);
                h[k] = *(unsigned*)&p;
            }
#pragma unroll
            for (int o = 16; o; o >>= 1) {
                Z += __shfl_xor_sync(0xffffffffu, Z, o);
                S += __shfl_xor_sync(0xffffffffu, S, o);
            }
            dst[0] = make_uint4(h[0], h[1], h[2], h[3]);
            dst[1] = make_uint4(h[4], h[5], h[6], h[7]);
            float logZ = __logf(Z);
            float entropy = logZ - S / Z;
            float conf = 1.f - entropy * 0.16029938f;     // 1/ln(512)
            if (lane == 0) {
                sCoef[r] = (1.f - conf) / Z;              // gate / Z
                outc[row] = conf;
            }
        } else {
            dst[0] = make_uint4(0, 0, 0, 0);
            dst[1] = make_uint4(0, 0, 0, 0);
            if (lane == 0) sCoef[r] = 0.f;
        }
    }

    // ---- Phase B: acc = ehat @ P2, 16 K-chunks of 32, double-buffered
    float acc[4][4][4];
#pragma unroll
    for (int mt = 0; mt < 4; mt++)
#pragma unroll
        for (int nt = 0; nt < 4; nt++)
#pragma unroll
            for (int q = 0; q < 4; q++) acc[mt][nt][q] = 0.f;

    int colbase = warp * 32;
    // ldmatrix A base address: tile t4 = lane>>3 -> (row, koff)
    int t4 = lane >> 3, r8 = lane & 7;
    uint32_t aBase = sbase + SE_OFF +
        (((uint32_t)((t4 & 1) * 8 + r8)) * SE_STRIDE + (uint32_t)(t4 >> 1) * 8) * 2;

    for (int kc = 0; kc < 16; kc++) {
        int buf = kc & 1;
        CP_WAIT1();          // chunk kc resident
        __syncthreads();
        const __half* sBb = (const __half*)(smem + SB_OFF + buf * SB_BUF);
#pragma unroll
        for (int ks = 0; ks < 2; ks++) {
            unsigned a[4][4];
#pragma unroll
            for (int mt = 0; mt < 4; mt++)
                ldmatrix_x4(a[mt], aBase + (uint32_t)(mt * 16 * SE_STRIDE + kc * 32 + ks * 16) * 2);
#pragma unroll
            for (int nt = 0; nt < 4; nt++) {
                int col = colbase + nt * 8 + g;
                const char* bp = (const char*)sBb + col * 80 + (ks * 16 + 2 * tg) * 2;
                unsigned b0 = *(const unsigned*)bp;
                unsigned b1 = *(const unsigned*)(bp + 16);
#pragma unroll
                for (int mt = 0; mt < 4; mt++) mma_f16(acc[mt][nt], a[mt], b0, b1);
            }
        }
        __syncthreads();     // all warps done reading buf
        if (kc + 2 < 16) {
#pragma unroll
            for (int j = 0; j < 4; j++) {
                int idx = tid + j * 256;
                int nr = idx >> 2, seg = idx & 3;
                uint32_t dst = sbase + SB_OFF + buf * SB_BUF + nr * 80 + seg * 16;
                const char* src = P2c + ((size_t)nr * NB + (kc + 2) * 32 + seg * 8) * 2;
                CP_ASYNC16(dst, src);
            }
        }
        CP_COMMIT();         // one group per iteration (possibly empty)
    }

    // ---- Phase C: fragments -> smem fp32 [64][SH_STRIDE] (reuses sE/sB region)
    float* sH = (float*)smem;
#pragma unroll
    for (int mt = 0; mt < 4; mt++) {
        int rb = mt * 16;
#pragma unroll
        for (int nt = 0; nt < 4; nt++) {
            int cb = colbase + nt * 8 + 2 * tg;
            sH[(rb + g) * SH_STRIDE + cb]         = acc[mt][nt][0];
            sH[(rb + g) * SH_STRIDE + cb + 1]     = acc[mt][nt][1];
            sH[(rb + g + 8) * SH_STRIDE + cb]     = acc[mt][nt][2];
            sH[(rb + g + 8) * SH_STRIDE + cb + 1] = acc[mt][nt][3];
        }
    }
    __syncthreads();

    // ---- LayerNorm per row (each warp: 8 rows)
    float gam[8], bet[8];
#pragma unroll
    for (int k = 0; k < 8; k++) { gam[k] = gamma[lane + 32 * k]; bet[k] = beta[lane + 32 * k]; }
#pragma unroll
    for (int rr = 0; rr < 8; rr++) {
        int r = warp * 8 + rr;
        int row = row0 + r;
        if (row < n) {
            float coef = sCoef[r];
            const float* hrow = hfused + (size_t)row * ND;
            float x[8];
            float s = 0.f, s2 = 0.f;
#pragma unroll
            for (int k = 0; k < 8; k++) {
                int c = lane + 32 * k;
                x[k] = hrow[c] + coef * sH[r * SH_STRIDE + c];
                s += x[k]; s2 += x[k] * x[k];
            }
#pragma unroll
            for (int o = 16; o; o >>= 1) {
                s += __shfl_xor_sync(0xffffffffu, s, o);
                s2 += __shfl_xor_sync(0xffffffffu, s2, o);
            }
            float mean = s * (1.f / ND);
            float var = s2 * (1.f / ND) - mean * mean;
            float rstd = rsqrtf(var + 1e-5f);
            float* orow = outh + (size_t)row * ND;
#pragma unroll
            for (int k = 0; k < 8; k++) {
                int c = lane + 32 * k;
                orow[c] = (x[k] - mean) * rstd * gam[k] + bet[k];
            }
        }
    }
}

// ---------------- launch ----------------
extern "C" void kernel_launch(void* const* d_in, const int* in_sizes, int n_in,
                              void* d_out, int out_size) {
    const float* h_fused = (const float*)d_in[0];
    const float* V       = (const float*)d_in[1];
    const float* logits  = (const float*)d_in[2];
    const int*   bk32    = (const int*)d_in[3];
    const float* Wr      = (const float*)d_in[4];
    const float* gamma   = (const float*)d_in[5];
    const float* beta    = (const float*)d_in[6];
    int n = in_sizes[0] / ND;

    float* outh = (float*)d_out;
    float* outc = outh + (size_t)n * ND;

    cudaFuncSetAttribute(main_kernel, cudaFuncAttributeMaxDynamicSharedMemorySize,
                         SMEM_TOTAL);

    counts_kernel<<<NCNT_BLK, 256>>>(bk32, n);                       // 1
    scan_kernel<<<1, NB>>>(n);                                       // 2
    scatter_kernel<<<(n + 511) / 512, 512>>>(bk32, n);               // 3
    bucket_sum_kernel<<<NB, 256>>>(V);                               // 4
    p2_kernel<<<NB, 256>>>(Wr, n);                                   // 5
    main_kernel<<<(n + 63) / 64, 256, SMEM_TOTAL>>>(logits, h_fused, gamma, beta,
                                                    outh, outc, n);  // 6 (ncu window)
}

// round 10
// speedup vs baseline: 3.5729x; 1.1116x over previous
#include <cuda_runtime.h>
#include <cuda_fp16.h>
#include <cstdint>

#define NB 512   // buckets
#define ND 256   // feature dim
#define NMAX 100352
#define NCNT_BLK 56

#define SE_STRIDE 520          // halves per row of exp tile (512 + 8 pad)
#define SE_OFF 0               // 64 x 520 halves = 66560 B
#define SB_OFF 66560           // per-warp B double buffers: 8 x 2 x 2560 B
#define SB_WARP 5120           // 2 bufs x 2560
#define SB_BUF 2560            // 32 n-rows x 80 B
#define XCOEF_OFF 107520       // 64 floats
#define SMEM_TOTAL (107520 + 256 + 32)
#define SH_STRIDE 264          // fp32 epilogue tile stride (overlaps sE/sB region)

// ---------------- device scratch (no allocation allowed) ----------------
__device__ float g_sums[NB * ND];
__device__ float g_counts[NB];
__device__ int   g_pcnt[NCNT_BLK][NB];
__device__ int   g_off[NB + 1];
__device__ int   g_cursor[NB];
__device__ int   g_perm[NMAX];
__device__ __align__(16) __half g_P2t[ND * NB];  // (proto @ W_r^T)^T fp16, [d2][b]

// ---------------- helpers ----------------
__device__ __forceinline__ uint32_t smem_u32(const void* p) {
    uint32_t a;
    asm("{ .reg .u64 t; cvta.to.shared.u64 t, %1; cvt.u32.u64 %0, t; }" : "=r"(a) : "l"(p));
    return a;
}
__device__ __forceinline__ void mma_f16(float* c, const unsigned* a,
                                        unsigned b0, unsigned b1) {
    asm("mma.sync.aligned.m16n8k16.row.col.f32.f16.f16.f32 "
        "{%0,%1,%2,%3},{%4,%5,%6,%7},{%8,%9},{%0,%1,%2,%3};"
        : "+f"(c[0]), "+f"(c[1]), "+f"(c[2]), "+f"(c[3])
        : "r"(a[0]), "r"(a[1]), "r"(a[2]), "r"(a[3]), "r"(b0), "r"(b1));
}
__device__ __forceinline__ void ldmatrix_x4(unsigned* r, uint32_t addr) {
    asm volatile("ldmatrix.sync.aligned.m8n8.x4.shared.b16 {%0,%1,%2,%3}, [%4];"
        : "=r"(r[0]), "=r"(r[1]), "=r"(r[2]), "=r"(r[3]) : "r"(addr));
}
#define CP_ASYNC16(dst, src) \
    asm volatile("cp.async.cg.shared.global [%0], [%1], 16;" :: "r"(dst), "l"(src))
#define CP_COMMIT() asm volatile("cp.async.commit_group;" ::: "memory")
#define CP_WAIT1()  asm volatile("cp.async.wait_group 1;" ::: "memory")

// ---------------- dtype detect (warp-parallel) ----------------
__device__ __forceinline__ int detect_stride(const int* __restrict__ bk, int n) {
    int lane = threadIdx.x & 31;
    int acc = 0;
    int lim = min(256, n / 2);
    for (int j = lane; j < lim; j += 32) acc |= bk[2 * j + 1];
#pragma unroll
    for (int o = 16; o; o >>= 1) acc |= __shfl_xor_sync(0xffffffffu, acc, o);
    return acc ? 1 : 2;
}

// ---------------- 1: per-block bucket counts ----------------
__global__ void counts_kernel(const int* __restrict__ bk, int n) {
    __shared__ int sc[NB];
    __shared__ int sstride;
    if (threadIdx.x < 32) {
        int s = detect_stride(bk, n);
        if (threadIdx.x == 0) sstride = s;
    }
    for (int i = threadIdx.x; i < NB; i += 256) sc[i] = 0;
    __syncthreads();
    int stride = sstride;
    for (int i = blockIdx.x * 256 + threadIdx.x; i < n; i += NCNT_BLK * 256) {
        unsigned b = (unsigned)bk[(size_t)i * stride];
        if (b < NB) atomicAdd(&sc[b], 1);
    }
    __syncthreads();
    for (int i = threadIdx.x; i < NB; i += 256) g_pcnt[blockIdx.x][i] = sc[i];
}

// ---------------- 2: reduce + scan (1 CTA) ----------------
__global__ void scan_kernel(int n) {
    __shared__ int s[NB];
    int t = threadIdx.x;
    int cnt = 0;
    for (int b = 0; b < NCNT_BLK; b++) cnt += g_pcnt[b][t];
    s[t] = cnt;
    __syncthreads();
#pragma unroll
    for (int o = 1; o < NB; o <<= 1) {
        int v = (t >= o) ? s[t - o] : 0;
        __syncthreads();
        s[t] += v;
        __syncthreads();
    }
    int excl = s[t] - cnt;
    g_off[t] = excl;
    g_cursor[t] = excl;
    g_counts[t] = (float)cnt;
    if (t == NB - 1) g_off[NB] = s[t];
}

// ---------------- 3: scatter permutation ----------------
__global__ void scatter_kernel(const int* __restrict__ bk, int n) {
    __shared__ int sstride;
    if (threadIdx.x < 32) {
        int s = detect_stride(bk, n);
        if (threadIdx.x == 0) sstride = s;
    }
    __syncthreads();
    int stride = sstride;
    int i = blockIdx.x * blockDim.x + threadIdx.x;
    if (i < n) {
        unsigned b = (unsigned)bk[(size_t)i * stride];
        if (b < NB) {
            int pos = atomicAdd(&g_cursor[b], 1);
            if ((unsigned)pos < (unsigned)NMAX) g_perm[pos] = i;
        }
    }
}

// ---------------- 4: per-bucket column sums (no atomics, deep MLP) ----------------
__global__ __launch_bounds__(256) void bucket_sum_kernel(const float* __restrict__ V) {
    int b = blockIdx.x, t = threadIdx.x;
    int s0 = g_off[b], s1 = g_off[b + 1];
    float acc = 0.f;
    int i = s0;
    for (; i + 16 <= s1; i += 16) {
        int r[16];
#pragma unroll
        for (int j = 0; j < 16; j++) r[j] = g_perm[i + j];
#pragma unroll
        for (int j = 0; j < 16; j++) acc += V[(size_t)r[j] * ND + t];
    }
    for (; i < s1; i++) acc += V[(size_t)g_perm[i] * ND + t];
    g_sums[b * ND + t] = acc;
}

// ---------------- 5: P2^T fp16 (with lazy global-mean fallback) ----------------
__global__ void p2_kernel(const float* __restrict__ Wr, int n) {
    __shared__ __align__(16) float sp[ND];
    int b = blockIdx.x, t = threadIdx.x;
    float cnt = g_counts[b];
    float val;
    if (cnt > 0.f) {
        val = g_sums[(size_t)b * ND + t] / cnt;
    } else {  // statistically never taken at N=100k, B=512; correct if it is
        float s = 0.f;
        for (int bb = 0; bb < NB; bb++) s += g_sums[(size_t)bb * ND + t];
        val = s / (float)n;
    }
    sp[t] = val;
    __syncthreads();
    const float4* w4 = (const float4*)(Wr + (size_t)t * ND);
    const float4* p4 = (const float4*)sp;
    float acc = 0.f;
#pragma unroll 8
    for (int d = 0; d < ND / 4; d++) {
        float4 a = p4[d], w = w4[d];
        acc += a.x * w.x + a.y * w.y + a.z * w.z + a.w * w.w;
    }
    g_P2t[(size_t)t * NB + b] = __float2half(acc);
}

// ---------------- 6: fused main (fp16 mma + warp-private cp.async pipeline) ----------------
// CTA: 64 rows. Phase A: softmax -> fp16 exp tile (warp's B prefetch in flight).
// Phase B: 64x256x512 GEMM, m16n8k16; each warp stages ONLY its own 32-col
// B slice (warp-private double buffer) -> no CTA barriers in the loop.
// Phase C: gate+add h_fused, LayerNorm.
__global__ __launch_bounds__(256, 2) void main_kernel(
    const float* __restrict__ logits, const float* __restrict__ hfused,
    const float* __restrict__ gamma, const float* __restrict__ beta,
    float* __restrict__ outh, float* __restrict__ outc, int n) {
    extern __shared__ __align__(16) char smem[];
    __half* sE = (__half*)(smem + SE_OFF);
    float* sCoef = (float*)(smem + XCOEF_OFF);
    uint32_t sbase = smem_u32(smem);

    int row0 = blockIdx.x * 64;
    int tid = threadIdx.x, lane = tid & 31, warp = tid >> 5;
    int g = lane >> 2, tg = lane & 3;
    int colbase = warp * 32;

    const char* P2c = (const char*)g_P2t;
    uint32_t sbW = sbase + SB_OFF + warp * SB_WARP;
    // per-warp stage of chunk kc into buf: 32 n-rows x 64 B, 4 x 16B per lane
    int stg_nr = lane >> 2, stg_seg = lane & 3;          // pattern per j-step
#define STAGE_CHUNK(kc, buf)                                                     \
    do {                                                                         \
        _Pragma("unroll")                                                        \
        for (int j = 0; j < 4; j++) {                                            \
            int nr = stg_nr + j * 8;                                             \
            uint32_t dst = sbW + (buf) * SB_BUF + nr * 80 + stg_seg * 16;        \
            const char* src = P2c +                                              \
                ((size_t)(colbase + nr) * NB + (kc) * 32 + stg_seg * 8) * 2;     \
            CP_ASYNC16(dst, src);                                                \
        }                                                                        \
        CP_COMMIT();                                                             \
    } while (0)

    // ---- prefetch B chunks 0 and 1 (overlaps Phase A) ----
    STAGE_CHUNK(0, 0);
    STAGE_CHUNK(1, 1);

    // ---- Phase A: per-row softmax stats (each warp: 8 rows; lane owns 16 cols)
#pragma unroll
    for (int rr = 0; rr < 8; rr++) {
        int r = warp * 8 + rr;
        int row = row0 + r;
        uint4* dst = (uint4*)(sE + r * SE_STRIDE + lane * 16);
        if (row < n) {
            const float* lrow = logits + (size_t)row * NB + lane * 16;
            float v[16];
#pragma unroll
            for (int q = 0; q < 4; q++) {
                float4 f = *(const float4*)(lrow + 4 * q);
                v[4 * q] = f.x; v[4 * q + 1] = f.y; v[4 * q + 2] = f.z; v[4 * q + 3] = f.w;
            }
            float m = v[0];
#pragma unroll
            for (int k = 1; k < 16; k++) m = fmaxf(m, v[k]);
#pragma unroll
            for (int o = 16; o; o >>= 1) m = fmaxf(m, __shfl_xor_sync(0xffffffffu, m, o));
            float Z = 0.f, S = 0.f;
            unsigned h[8];
#pragma unroll
            for (int k = 0; k < 8; k++) {
                float t0 = v[2 * k] - m, t1 = v[2 * k + 1] - m;
                float e0 = __expf(t0), e1 = __expf(t1);
                Z += e0 + e1; S += e0 * t0 + e1 * t1;
                __half2 p = __floats2half2_rn(e0, e1);
                h[k] = *(unsigned*)&p;
            }
#pragma unroll
            for (int o = 16; o; o >>= 1) {
                Z += __shfl_xor_sync(0xffffffffu, Z, o);
                S += __shfl_xor_sync(0xffffffffu, S, o);
            }
            dst[0] = make_uint4(h[0], h[1], h[2], h[3]);
            dst[1] = make_uint4(h[4], h[5], h[6], h[7]);
            float logZ = __logf(Z);
            float entropy = logZ - S / Z;
            float conf = 1.f - entropy * 0.16029938f;     // 1/ln(512)
            if (lane == 0) {
                sCoef[r] = (1.f - conf) / Z;              // gate / Z
                outc[row] = conf;
            }
        } else {
            dst[0] = make_uint4(0, 0, 0, 0);
            dst[1] = make_uint4(0, 0, 0, 0);
            if (lane == 0) sCoef[r] = 0.f;
        }
    }
    __syncthreads();   // sE complete (A fragments cross warps)

    // ---- Phase B: acc = ehat @ P2, 16 K-chunks of 32, warp-private pipeline
    float acc[4][4][4];
#pragma unroll
    for (int mt = 0; mt < 4; mt++)
#pragma unroll
        for (int nt = 0; nt < 4; nt++)
#pragma unroll
            for (int q = 0; q < 4; q++) acc[mt][nt][q] = 0.f;

    // ldmatrix A base: tile t4 = lane>>3 -> (row block, k offset)
    int t4 = lane >> 3, r8 = lane & 7;
    uint32_t aBase = sbase + SE_OFF +
        (((uint32_t)((t4 & 1) * 8 + r8)) * SE_STRIDE + (uint32_t)(t4 >> 1) * 8) * 2;
    // ldmatrix B base: tile l>>3: nt = pair*2 + (tile>>1), koff = (tile&1)*8
    uint32_t bTileOff = ((uint32_t)((t4 >> 1) * 8 + r8)) * 80u + (uint32_t)(t4 & 1) * 16u;

    for (int kc = 0; kc < 16; kc++) {
        int buf = kc & 1;
        CP_WAIT1();          // this warp's chunk kc resident
        uint32_t bBuf = sbW + buf * SB_BUF + bTileOff;
#pragma unroll
        for (int ks = 0; ks < 2; ks++) {
            unsigned a[4][4];
#pragma unroll
            for (int mt = 0; mt < 4; mt++)
                ldmatrix_x4(a[mt], aBase + (uint32_t)(mt * 16 * SE_STRIDE + kc * 32 + ks * 16) * 2);
            unsigned bb[8];
            ldmatrix_x4(bb,     bBuf + ks * 32);              // nt 0,1
            ldmatrix_x4(bb + 4, bBuf + 16 * 80 + ks * 32);    // nt 2,3
#pragma unroll
            for (int nt = 0; nt < 4; nt++)
#pragma unroll
                for (int mt = 0; mt < 4; mt++)
                    mma_f16(acc[mt][nt], a[mt], bb[2 * nt], bb[2 * nt + 1]);
        }
        // in-warp program order: ldmatrix reads of buf are done; safe to refill
        if (kc + 2 < 16) STAGE_CHUNK(kc + 2, buf);
        else CP_COMMIT();    // empty group keeps wait_group accounting
    }
    __syncthreads();   // all warps done reading sE/sB before overwrite

    // ---- Phase C: fragments -> smem fp32 [64][SH_STRIDE] (reuses sE/sB region)
    float* sH = (float*)smem;
#pragma unroll
    for (int mt = 0; mt < 4; mt++) {
        int rb = mt * 16;
#pragma unroll
        for (int nt = 0; nt < 4; nt++) {
            int cb = colbase + nt * 8 + 2 * tg;
            sH[(rb + g) * SH_STRIDE + cb]         = acc[mt][nt][0];
            sH[(rb + g) * SH_STRIDE + cb + 1]     = acc[mt][nt][1];
            sH[(rb + g + 8) * SH_STRIDE + cb]     = acc[mt][nt][2];
            sH[(rb + g + 8) * SH_STRIDE + cb + 1] = acc[mt][nt][3];
        }
    }
    __syncthreads();

    // ---- LayerNorm per row (each warp: 8 rows)
    float gam[8], bet[8];
#pragma unroll
    for (int k = 0; k < 8; k++) { gam[k] = gamma[lane + 32 * k]; bet[k] = beta[lane + 32 * k]; }
#pragma unroll
    for (int rr = 0; rr < 8; rr++) {
        int r = warp * 8 + rr;
        int row = row0 + r;
        if (row < n) {
            float coef = sCoef[r];
            const float* hrow = hfused + (size_t)row * ND;
            float x[8];
            float s = 0.f, s2 = 0.f;
#pragma unroll
            for (int k = 0; k < 8; k++) {
                int c = lane + 32 * k;
                x[k] = hrow[c] + coef * sH[r * SH_STRIDE + c];
                s += x[k]; s2 += x[k] * x[k];
            }
#pragma unroll
            for (int o = 16; o; o >>= 1) {
                s += __shfl_xor_sync(0xffffffffu, s, o);
                s2 += __shfl_xor_sync(0xffffffffu, s2, o);
            }
            float mean = s * (1.f / ND);
            float var = s2 * (1.f / ND) - mean * mean;
            float rstd = rsqrtf(var + 1e-5f);
            float* orow = outh + (size_t)row * ND;
#pragma unroll
            for (int k = 0; k < 8; k++) {
                int c = lane + 32 * k;
                orow[c] = (x[k] - mean) * rstd * gam[k] + bet[k];
            }
        }
    }
}

// ---------------- launch ----------------
extern "C" void kernel_launch(void* const* d_in, const int* in_sizes, int n_in,
                              void* d_out, int out_size) {
    const float* h_fused = (const float*)d_in[0];
    const float* V       = (const float*)d_in[1];
    const float* logits  = (const float*)d_in[2];
    const int*   bk32    = (const int*)d_in[3];
    const float* Wr      = (const float*)d_in[4];
    const float* gamma   = (const float*)d_in[5];
    const float* beta    = (const float*)d_in[6];
    int n = in_sizes[0] / ND;

    float* outh = (float*)d_out;
    float* outc = outh + (size_t)n * ND;

    cudaFuncSetAttribute(main_kernel, cudaFuncAttributeMaxDynamicSharedMemorySize,
                         SMEM_TOTAL);

    counts_kernel<<<NCNT_BLK, 256>>>(bk32, n);                       // 1
    scan_kernel<<<1, NB>>>(n);                                       // 2
    scatter_kernel<<<(n + 511) / 512, 512>>>(bk32, n);               // 3
    bucket_sum_kernel<<<NB, 256>>>(V);                               // 4
    p2_kernel<<<NB, 256>>>(Wr, n);                                   // 5
    main_kernel<<<(n + 63) / 64, 256, SMEM_TOTAL>>>(logits, h_fused, gamma, beta,
                                                    outh, outc, n);  // 6
}

// round 12
// speedup vs baseline: 3.9658x; 1.1100x over previous
#include <cuda_runtime.h>
#include <cuda_fp16.h>
#include <cstdint>

#define NB 512   // buckets
#define ND 256   // feature dim
#define NMAX 100352
#define NCNT_BLK 56

#define SE_STRIDE 520          // halves per row of exp tile (512 + 8 pad)
#define SE_OFF 0               // 64 x 520 halves = 66560 B
#define SB_OFF 66560           // per-warp B double buffers: 8 x 2 x 2560 B
#define SB_WARP 5120           // 2 bufs x 2560
#define SB_BUF 2560            // 32 n-rows x 80 B
#define XCOEF_OFF 107520       // 64 floats
#define SMEM_TOTAL (107520 + 256 + 32)
#define SH_STRIDE 264          // fp32 epilogue tile stride (overlaps sE/sB region)

// ---------------- device scratch (no allocation allowed) ----------------
__device__ float g_sums[NB * ND];
__device__ float g_counts[NB];
__device__ int   g_pcnt[NCNT_BLK][NB];
__device__ int   g_off[NB + 1];
__device__ int   g_cursor[NB];
__device__ int   g_perm[NMAX];
__device__ int   g_tick1;   // countscan ticket (reset each run)
__device__ int   g_tick2;   // bucketsum_p2 ticket (reset each run)
__device__ __align__(16) __half g_P2t[ND * NB];  // (proto @ W_r^T)^T fp16, [d2][b]

// ---------------- helpers ----------------
__device__ __forceinline__ uint32_t smem_u32(const void* p) {
    uint32_t a;
    asm("{ .reg .u64 t; cvta.to.shared.u64 t, %1; cvt.u32.u64 %0, t; }" : "=r"(a) : "l"(p));
    return a;
}
__device__ __forceinline__ void mma_f16(float* c, const unsigned* a,
                                        unsigned b0, unsigned b1) {
    asm("mma.sync.aligned.m16n8k16.row.col.f32.f16.f16.f32 "
        "{%0,%1,%2,%3},{%4,%5,%6,%7},{%8,%9},{%0,%1,%2,%3};"
        : "+f"(c[0]), "+f"(c[1]), "+f"(c[2]), "+f"(c[3])
        : "r"(a[0]), "r"(a[1]), "r"(a[2]), "r"(a[3]), "r"(b0), "r"(b1));
}
__device__ __forceinline__ void ldmatrix_x4(unsigned* r, uint32_t addr) {
    asm volatile("ldmatrix.sync.aligned.m8n8.x4.shared.b16 {%0,%1,%2,%3}, [%4];"
        : "=r"(r[0]), "=r"(r[1]), "=r"(r[2]), "=r"(r[3]) : "r"(addr));
}
#define CP_ASYNC16(dst, src) \
    asm volatile("cp.async.cg.shared.global [%0], [%1], 16;" :: "r"(dst), "l"(src))
#define CP_COMMIT() asm volatile("cp.async.commit_group;" ::: "memory")
#define CP_WAIT1()  asm volatile("cp.async.wait_group 1;" ::: "memory")

// ---------------- dtype detect (warp-parallel) ----------------
__device__ __forceinline__ int detect_stride(const int* __restrict__ bk, int n) {
    int lane = threadIdx.x & 31;
    int acc = 0;
    int lim = min(256, n / 2);
    for (int j = lane; j < lim; j += 32) acc |= bk[2 * j + 1];
#pragma unroll
    for (int o = 16; o; o >>= 1) acc |= __shfl_xor_sync(0xffffffffu, acc, o);
    return acc ? 1 : 2;
}

// ---------------- 1: counts + scan (last-CTA ticket) ----------------
__global__ __launch_bounds__(512) void countscan_kernel(const int* __restrict__ bk, int n) {
    __shared__ int sc[NB];
    __shared__ int sstride;
    __shared__ int sticket;
    int tid = threadIdx.x;
    if (tid < 32) {
        int s = detect_stride(bk, n);
        if (tid == 0) sstride = s;
    }
    sc[tid] = 0;
    __syncthreads();
    int stride = sstride;
    for (int i = blockIdx.x * 512 + tid; i < n; i += NCNT_BLK * 512) {
        unsigned b = (unsigned)bk[(size_t)i * stride];
        if (b < NB) atomicAdd(&sc[b], 1);
    }
    __syncthreads();
    g_pcnt[blockIdx.x][tid] = sc[tid];
    __threadfence();
    if (tid == 0) sticket = atomicAdd(&g_tick1, 1);
    __syncthreads();
    if (sticket == NCNT_BLK - 1) {   // last CTA: reduce + scan
        int cnt = 0;
        for (int b = 0; b < NCNT_BLK; b++) cnt += g_pcnt[b][tid];
        sc[tid] = cnt;
        __syncthreads();
#pragma unroll
        for (int o = 1; o < NB; o <<= 1) {
            int v = (tid >= o) ? sc[tid - o] : 0;
            __syncthreads();
            sc[tid] += v;
            __syncthreads();
        }
        int excl = sc[tid] - cnt;
        g_off[tid] = excl;
        g_cursor[tid] = excl;
        g_counts[tid] = (float)cnt;
        if (tid == NB - 1) g_off[NB] = sc[tid];
        if (tid == 0) g_tick1 = 0;   // reset for next graph replay
    }
}

// ---------------- 2: scatter permutation ----------------
__global__ void scatter_kernel(const int* __restrict__ bk, int n) {
    __shared__ int sstride;
    if (threadIdx.x < 32) {
        int s = detect_stride(bk, n);
        if (threadIdx.x == 0) sstride = s;
    }
    __syncthreads();
    int stride = sstride;
    int i = blockIdx.x * blockDim.x + threadIdx.x;
    if (i < n) {
        unsigned b = (unsigned)bk[(size_t)i * stride];
        if (b < NB) {
            int pos = atomicAdd(&g_cursor[b], 1);
            if ((unsigned)pos < (unsigned)NMAX) g_perm[pos] = i;
        }
    }
}

// ---------------- 3: bucket sums + prototype + P2 row (fused) ----------------
// CTA b, 512 threads: t = col (0..255), h = row-half (0/1).
__global__ __launch_bounds__(512) void bucketsum_p2_kernel(
    const float* __restrict__ V, const float* __restrict__ Wr, int n) {
    __shared__ float spart[2][ND];
    __shared__ __align__(16) float sp[ND];
    __shared__ int sticket;
    int b = blockIdx.x;
    int tid = threadIdx.x, t = tid & 255, h = tid >> 8;
    int lane = tid & 31, warp = tid >> 5;

    int s0 = g_off[b], s1 = g_off[b + 1];
    int len = s1 - s0;
    int half = (len + 1) >> 1;
    int hs = s0 + h * half;
    int he = min(s1, hs + half);
    float acc = 0.f;
    int i = hs;
    for (; i + 8 <= he; i += 8) {
        int r[8];
#pragma unroll
        for (int j = 0; j < 8; j++) r[j] = g_perm[i + j];
#pragma unroll
        for (int j = 0; j < 8; j++) acc += V[(size_t)r[j] * ND + t];
    }
    for (; i < he; i++) acc += V[(size_t)g_perm[i] * ND + t];
    spart[h][t] = acc;
    __syncthreads();

    float cnt = (float)len;
    if (h == 0) {
        float tot = spart[0][t] + spart[1][t];
        g_sums[(size_t)b * ND + t] = tot;
        sp[t] = (len > 0) ? tot / cnt : 0.f;
    }
    __syncthreads();

    // P2 row: warp w computes rows [w*16, w*16+16); lane covers 8 contiguous d.
    const float4* sp4 = (const float4*)sp;
    if (len > 0) {
        for (int rr = 0; rr < 16; rr++) {
            int r = warp * 16 + rr;
            const float4* w4 = (const float4*)(Wr + (size_t)r * ND);
            float4 p0 = sp4[lane * 2], p1 = sp4[lane * 2 + 1];
            float4 w0 = w4[lane * 2], w1 = w4[lane * 2 + 1];
            float part = p0.x * w0.x + p0.y * w0.y + p0.z * w0.z + p0.w * w0.w +
                         p1.x * w1.x + p1.y * w1.y + p1.z * w1.z + p1.w * w1.w;
#pragma unroll
            for (int o = 16; o; o >>= 1) part += __shfl_xor_sync(0xffffffffu, part, o);
            if (lane == 0) g_P2t[(size_t)r * NB + b] = __float2half(part);
        }
    }
    // ticket: last CTA fixes up empty buckets (gmean prototype); resets ticket.
    __threadfence();
    if (tid == 0) sticket = atomicAdd(&g_tick2, 1);
    __syncthreads();
    if (sticket == NB - 1) {
        int any_empty = 0;
        for (int bb = tid; bb < NB; bb += 512) if (g_counts[bb] == 0.f) any_empty = 1;
        __syncthreads();
        spart[0][0] = 0.f;  // reuse as flag
        __syncthreads();
        if (any_empty) spart[0][0] = 1.f;
        __syncthreads();
        if (spart[0][0] != 0.f) {      // statistically never taken
            if (h == 0) {
                float s = 0.f;
                for (int bb = 0; bb < NB; bb++) s += g_sums[(size_t)bb * ND + t];
                sp[t] = s / (float)n;
            }
            __syncthreads();
            for (int bb = 0; bb < NB; bb++) {
                if (g_counts[bb] != 0.f) continue;
                for (int rr = 0; rr < 16; rr++) {
                    int r = warp * 16 + rr;
                    const float4* w4 = (const float4*)(Wr + (size_t)r * ND);
                    float4 p0 = sp4[lane * 2], p1 = sp4[lane * 2 + 1];
                    float4 w0 = w4[lane * 2], w1 = w4[lane * 2 + 1];
                    float part = p0.x * w0.x + p0.y * w0.y + p0.z * w0.z + p0.w * w0.w +
                                 p1.x * w1.x + p1.y * w1.y + p1.z * w1.z + p1.w * w1.w;
#pragma unroll
                    for (int o = 16; o; o >>= 1) part += __shfl_xor_sync(0xffffffffu, part, o);
                    if (lane == 0) g_P2t[(size_t)r * NB + bb] = __float2half(part);
                }
            }
        }
        if (tid == 0) g_tick2 = 0;
    }
}

// ---------------- 4: fused main (fp16 mma + warp-private cp.async pipeline) ----------------
__global__ __launch_bounds__(256, 2) void main_kernel(
    const float* __restrict__ logits, const float* __restrict__ hfused,
    const float* __restrict__ gamma, const float* __restrict__ beta,
    float* __restrict__ outh, float* __restrict__ outc, int n) {
    extern __shared__ __align__(16) char smem[];
    __half* sE = (__half*)(smem + SE_OFF);
    float* sCoef = (float*)(smem + XCOEF_OFF);
    uint32_t sbase = smem_u32(smem);

    int row0 = blockIdx.x * 64;
    int tid = threadIdx.x, lane = tid & 31, warp = tid >> 5;
    int g = lane >> 2, tg = lane & 3;
    int colbase = warp * 32;

    const char* P2c = (const char*)g_P2t;
    uint32_t sbW = sbase + SB_OFF + warp * SB_WARP;
    int stg_nr = lane >> 2, stg_seg = lane & 3;
#define STAGE_CHUNK(kc, buf)                                                     \
    do {                                                                         \
        _Pragma("unroll")                                                        \
        for (int j = 0; j < 4; j++) {                                            \
            int nr = stg_nr + j * 8;                                             \
            uint32_t dst = sbW + (buf) * SB_BUF + nr * 80 + stg_seg * 16;        \
            const char* src = P2c +                                              \
                ((size_t)(colbase + nr) * NB + (kc) * 32 + stg_seg * 8) * 2;     \
            CP_ASYNC16(dst, src);                                                \
        }                                                                        \
        CP_COMMIT();                                                             \
    } while (0)

    STAGE_CHUNK(0, 0);
    STAGE_CHUNK(1, 1);

    // ---- Phase A: per-row softmax stats (each warp: 8 rows; lane owns 16 cols)
#pragma unroll
    for (int rr = 0; rr < 8; rr++) {
        int r = warp * 8 + rr;
        int row = row0 + r;
        uint4* dst = (uint4*)(sE + r * SE_STRIDE + lane * 16);
        if (row < n) {
            const float* lrow = logits + (size_t)row * NB + lane * 16;
            float v[16];
#pragma unroll
            for (int q = 0; q < 4; q++) {
                float4 f = *(const float4*)(lrow + 4 * q);
                v[4 * q] = f.x; v[4 * q + 1] = f.y; v[4 * q + 2] = f.z; v[4 * q + 3] = f.w;
            }
            float m = v[0];
#pragma unroll
            for (int k = 1; k < 16; k++) m = fmaxf(m, v[k]);
#pragma unroll
            for (int o = 16; o; o >>= 1) m = fmaxf(m, __shfl_xor_sync(0xffffffffu, m, o));
            float Z = 0.f, S = 0.f;
            unsigned h[8];
#pragma unroll
            for (int k = 0; k < 8; k++) {
                float t0 = v[2 * k] - m, t1 = v[2 * k + 1] - m;
                float e0 = __expf(t0), e1 = __expf(t1);
                Z += e0 + e1; S += e0 * t0 + e1 * t1;
                __half2 p = __floats2half2_rn(e0, e1);
                h[k] = *(unsigned*)&p;
            }
#pragma unroll
            for (int o = 16; o; o >>= 1) {
                Z += __shfl_xor_sync(0xffffffffu, Z, o);
                S += __shfl_xor_sync(0xffffffffu, S, o);
            }
            dst[0] = make_uint4(h[0], h[1], h[2], h[3]);
            dst[1] = make_uint4(h[4], h[5], h[6], h[7]);
            float logZ = __logf(Z);
            float entropy = logZ - S / Z;
            float conf = 1.f - entropy * 0.16029938f;     // 1/ln(512)
            if (lane == 0) {
                sCoef[r] = (1.f - conf) / Z;              // gate / Z
                outc[row] = conf;
            }
        } else {
            dst[0] = make_uint4(0, 0, 0, 0);
            dst[1] = make_uint4(0, 0, 0, 0);
            if (lane == 0) sCoef[r] = 0.f;
        }
    }
    __syncthreads();   // sE complete (A fragments cross warps)

    // ---- Phase B: acc = ehat @ P2, 16 K-chunks of 32, warp-private pipeline
    float acc[4][4][4];
#pragma unroll
    for (int mt = 0; mt < 4; mt++)
#pragma unroll
        for (int nt = 0; nt < 4; nt++)
#pragma unroll
            for (int q = 0; q < 4; q++) acc[mt][nt][q] = 0.f;

    int t4 = lane >> 3, r8 = lane & 7;
    uint32_t aBase = sbase + SE_OFF +
        (((uint32_t)((t4 & 1) * 8 + r8)) * SE_STRIDE + (uint32_t)(t4 >> 1) * 8) * 2;
    uint32_t bTileOff = ((uint32_t)((t4 >> 1) * 8 + r8)) * 80u + (uint32_t)(t4 & 1) * 16u;

    for (int kc = 0; kc < 16; kc++) {
        int buf = kc & 1;
        CP_WAIT1();
        uint32_t bBuf = sbW + buf * SB_BUF + bTileOff;
#pragma unroll
        for (int ks = 0; ks < 2; ks++) {
            unsigned a[4][4];
#pragma unroll
            for (int mt = 0; mt < 4; mt++)
                ldmatrix_x4(a[mt], aBase + (uint32_t)(mt * 16 * SE_STRIDE + kc * 32 + ks * 16) * 2);
            unsigned bb[8];
            ldmatrix_x4(bb,     bBuf + ks * 32);              // nt 0,1
            ldmatrix_x4(bb + 4, bBuf + 16 * 80 + ks * 32);    // nt 2,3
#pragma unroll
            for (int nt = 0; nt < 4; nt++)
#pragma unroll
                for (int mt = 0; mt < 4; mt++)
                    mma_f16(acc[mt][nt], a[mt], bb[2 * nt], bb[2 * nt + 1]);
        }
        if (kc + 2 < 16) STAGE_CHUNK(kc + 2, buf);
        else CP_COMMIT();
    }
    __syncthreads();

    // ---- Phase C: fragments -> smem fp32 [64][SH_STRIDE]
    float* sH = (float*)smem;
#pragma unroll
    for (int mt = 0; mt < 4; mt++) {
        int rb = mt * 16;
#pragma unroll
        for (int nt = 0; nt < 4; nt++) {
            int cb = colbase + nt * 8 + 2 * tg;
            sH[(rb + g) * SH_STRIDE + cb]         = acc[mt][nt][0];
            sH[(rb + g) * SH_STRIDE + cb + 1]     = acc[mt][nt][1];
            sH[(rb + g + 8) * SH_STRIDE + cb]     = acc[mt][nt][2];
            sH[(rb + g + 8) * SH_STRIDE + cb + 1] = acc[mt][nt][3];
        }
    }
    __syncthreads();

    // ---- LayerNorm per row (each warp: 8 rows)
    float gam[8], bet[8];
#pragma unroll
    for (int k = 0; k < 8; k++) { gam[k] = gamma[lane + 32 * k]; bet[k] = beta[lane + 32 * k]; }
#pragma unroll
    for (int rr = 0; rr < 8; rr++) {
        int r = warp * 8 + rr;
        int row = row0 + r;
        if (row < n) {
            float coef = sCoef[r];
            const float* hrow = hfused + (size_t)row * ND;
            float x[8];
            float s = 0.f, s2 = 0.f;
#pragma unroll
            for (int k = 0; k < 8; k++) {
                int c = lane + 32 * k;
                x[k] = hrow[c] + coef * sH[r * SH_STRIDE + c];
                s += x[k]; s2 += x[k] * x[k];
            }
#pragma unroll
            for (int o = 16; o; o >>= 1) {
                s += __shfl_xor_sync(0xffffffffu, s, o);
                s2 += __shfl_xor_sync(0xffffffffu, s2, o);
            }
            float mean = s * (1.f / ND);
            float var = s2 * (1.f / ND) - mean * mean;
            float rstd = rsqrtf(var + 1e-5f);
            float* orow = outh + (size_t)row * ND;
#pragma unroll
            for (int k = 0; k < 8; k++) {
                int c = lane + 32 * k;
                orow[c] = (x[k] - mean) * rstd * gam[k] + bet[k];
            }
        }
    }
}

// ---------------- launch ----------------
extern "C" void kernel_launch(void* const* d_in, const int* in_sizes, int n_in,
                              void* d_out, int out_size) {
    const float* h_fused = (const float*)d_in[0];
    const float* V       = (const float*)d_in[1];
    const float* logits  = (const float*)d_in[2];
    const int*   bk32    = (const int*)d_in[3];
    const float* Wr      = (const float*)d_in[4];
    const float* gamma   = (const float*)d_in[5];
    const float* beta    = (const float*)d_in[6];
    int n = in_sizes[0] / ND;

    float* outh = (float*)d_out;
    float* outc = outh + (size_t)n * ND;

    cudaFuncSetAttribute(main_kernel, cudaFuncAttributeMaxDynamicSharedMemorySize,
                         SMEM_TOTAL);

    countscan_kernel<<<NCNT_BLK, 512>>>(bk32, n);                    // 1
    scatter_kernel<<<(n + 511) / 512, 512>>>(bk32, n);               // 2
    bucketsum_p2_kernel<<<NB, 512>>>(V, Wr, n);                      // 3
    main_kernel<<<(n + 63) / 64, 256, SMEM_TOTAL>>>(logits, h_fused, gamma, beta,
                                                    outh, outc, n);  // 4 (= overall #6, ncu window)
}